// round 10
// baseline (speedup 1.0000x reference)
#include <cuda_runtime.h>

// TensorProductUniform3x1d:
//   B=100000, NSEG=4, U=128, NPATH=20
//   out[b, i2, :] += c[p] * x0[b, i0[p], :] * x1[b, i1[p], :]
//
// R10: R9 config (float4, one warp per row, linear CTA order, default cache
// policy, fused shared W build) with 1024-thread blocks: same 32 resident
// warps/SM, but half the CTAs again (3125) -> fewer W builds / scheduling
// events, 64KB contiguous span per CTA. 256->512 blocks gave -1.6us on
// dur_us; extending the same lever.

#define NSEG 4
#define U 128
#define NPATH 20

__global__ __launch_bounds__(1024, 1)
void tp_uniform_fused_kernel(const float4* __restrict__ x0,
                             const float4* __restrict__ x1,
                             const float*  __restrict__ coeff,
                             const int*    __restrict__ idx,
                             float4* __restrict__ out,
                             int nrows) {
    __shared__ float sW[NSEG * NSEG * NSEG];

    // Build W[i2][i0][i1] = sum_p coeff[p] * [idx[p]==(i0,i1,i2)]
    int t = threadIdx.x;
    if (t < NSEG * NSEG * NSEG) {
        int i2 = t >> 4;
        int i0 = (t >> 2) & 3;
        int i1 = t & 3;
        float w = 0.0f;
        #pragma unroll
        for (int p = 0; p < NPATH; p++) {
            int p0 = __ldg(&idx[3 * p + 0]);
            int p1 = __ldg(&idx[3 * p + 1]);
            int p2 = __ldg(&idx[3 * p + 2]);
            if (p0 == i0 && p1 == i1 && p2 == i2) w += __ldg(&coeff[p]);
        }
        sW[t] = w;
    }
    __syncthreads();

    int gid  = blockIdx.x * blockDim.x + threadIdx.x;
    int row  = gid >> 5;
    int lane = gid & 31;
    if (row >= nrows) return;

    size_t base = (size_t)row * (NSEG * U / 4) + lane;  // float4 units

    // Front-batch all 8 loads (default cache policy — measured best).
    float4 a[NSEG], b[NSEG];
    #pragma unroll
    for (int s = 0; s < NSEG; s++) a[s] = __ldg(&x0[base + s * (U / 4)]);
    #pragma unroll
    for (int s = 0; s < NSEG; s++) b[s] = __ldg(&x1[base + s * (U / 4)]);

    // out[i2] = sum_{i0} a[i0] * ( sum_{i1} W[i2][i0][i1] * b[i1] )
    #pragma unroll
    for (int i2 = 0; i2 < NSEG; i2++) {
        float4 acc = make_float4(0.f, 0.f, 0.f, 0.f);
        #pragma unroll
        for (int i0 = 0; i0 < NSEG; i0++) {
            float4 tt = make_float4(0.f, 0.f, 0.f, 0.f);
            #pragma unroll
            for (int i1 = 0; i1 < NSEG; i1++) {
                float w = sW[(i2 * NSEG + i0) * NSEG + i1];
                tt.x = fmaf(w, b[i1].x, tt.x);
                tt.y = fmaf(w, b[i1].y, tt.y);
                tt.z = fmaf(w, b[i1].z, tt.z);
                tt.w = fmaf(w, b[i1].w, tt.w);
            }
            acc.x = fmaf(a[i0].x, tt.x, acc.x);
            acc.y = fmaf(a[i0].y, tt.y, acc.y);
            acc.z = fmaf(a[i0].z, tt.z, acc.z);
            acc.w = fmaf(a[i0].w, tt.w, acc.w);
        }
        out[base + i2 * (U / 4)] = acc;
    }
}

extern "C" void kernel_launch(void* const* d_in, const int* in_sizes, int n_in,
                              void* d_out, int out_size) {
    const float4* x0    = (const float4*)d_in[0];
    const float4* x1    = (const float4*)d_in[1];
    const float*  coeff = (const float*)d_in[2];
    const int*    idx   = (const int*)d_in[3];
    float4*       out   = (float4*)d_out;

    int nrows = in_sizes[0] / (NSEG * U);   // 100000

    int total_threads = nrows * 32;         // one warp per row
    int block = 1024;
    int grid  = (total_threads + block - 1) / block;
    tp_uniform_fused_kernel<<<grid, block>>>(x0, x1, coeff, idx, out, nrows);
}

// round 11
// speedup vs baseline: 1.0226x; 1.0226x over previous
#include <cuda_runtime.h>

// TensorProductUniform3x1d:
//   B=100000, NSEG=4, U=128, NPATH=20
//   out[b, i2, :] += c[p] * x0[b, i0[p], :] * x1[b, i1[p], :]
//
// FINAL (R11): measured-best configuration from the full lever scan —
//   * float4 accesses (128-bit; narrower widths regressed: R6)
//   * one warp per row, 8 front-batched loads (2 rows/warp regressed: R7)
//   * default cache policy (.cs / L2::256B regressed or neutral: R3-R5)
//   * linear CTA ordering (persistent grid-stride regressed: R8)
//   * 512-thread blocks, 2 CTAs/SM (block scan 256/512/1024 -> 512 best)
//   * fused per-block W build in shared (saves a second launch)
// Grid is exact: 100000 rows * 32 = 6250 * 512 threads, so no bounds guard.

#define NSEG 4
#define U 128
#define NPATH 20

__global__ __launch_bounds__(512, 2)
void tp_uniform_fused_kernel(const float4* __restrict__ x0,
                             const float4* __restrict__ x1,
                             const float*  __restrict__ coeff,
                             const int*    __restrict__ idx,
                             float4* __restrict__ out) {
    __shared__ float sW[NSEG * NSEG * NSEG];

    // Build W[i2][i0][i1] = sum_p coeff[p] * [idx[p]==(i0,i1,i2)]
    int t = threadIdx.x;
    if (t < NSEG * NSEG * NSEG) {
        int i2 = t >> 4;
        int i0 = (t >> 2) & 3;
        int i1 = t & 3;
        float w = 0.0f;
        #pragma unroll
        for (int p = 0; p < NPATH; p++) {
            int p0 = __ldg(&idx[3 * p + 0]);
            int p1 = __ldg(&idx[3 * p + 1]);
            int p2 = __ldg(&idx[3 * p + 2]);
            if (p0 == i0 && p1 == i1 && p2 == i2) w += __ldg(&coeff[p]);
        }
        sW[t] = w;
    }
    __syncthreads();

    int gid  = blockIdx.x * blockDim.x + threadIdx.x;
    int row  = gid >> 5;
    int lane = gid & 31;

    size_t base = (size_t)row * (NSEG * U / 4) + lane;  // float4 units

    // Front-batch all 8 loads (default cache policy — measured best).
    float4 a[NSEG], b[NSEG];
    #pragma unroll
    for (int s = 0; s < NSEG; s++) a[s] = __ldg(&x0[base + s * (U / 4)]);
    #pragma unroll
    for (int s = 0; s < NSEG; s++) b[s] = __ldg(&x1[base + s * (U / 4)]);

    // out[i2] = sum_{i0} a[i0] * ( sum_{i1} W[i2][i0][i1] * b[i1] )
    #pragma unroll
    for (int i2 = 0; i2 < NSEG; i2++) {
        float4 acc = make_float4(0.f, 0.f, 0.f, 0.f);
        #pragma unroll
        for (int i0 = 0; i0 < NSEG; i0++) {
            float4 tt = make_float4(0.f, 0.f, 0.f, 0.f);
            #pragma unroll
            for (int i1 = 0; i1 < NSEG; i1++) {
                float w = sW[(i2 * NSEG + i0) * NSEG + i1];
                tt.x = fmaf(w, b[i1].x, tt.x);
                tt.y = fmaf(w, b[i1].y, tt.y);
                tt.z = fmaf(w, b[i1].z, tt.z);
                tt.w = fmaf(w, b[i1].w, tt.w);
            }
            acc.x = fmaf(a[i0].x, tt.x, acc.x);
            acc.y = fmaf(a[i0].y, tt.y, acc.y);
            acc.z = fmaf(a[i0].z, tt.z, acc.z);
            acc.w = fmaf(a[i0].w, tt.w, acc.w);
        }
        out[base + i2 * (U / 4)] = acc;
    }
}

extern "C" void kernel_launch(void* const* d_in, const int* in_sizes, int n_in,
                              void* d_out, int out_size) {
    const float4* x0    = (const float4*)d_in[0];
    const float4* x1    = (const float4*)d_in[1];
    const float*  coeff = (const float*)d_in[2];
    const int*    idx   = (const int*)d_in[3];
    float4*       out   = (float4*)d_out;

    int nrows = in_sizes[0] / (NSEG * U);   // 100000

    int total_threads = nrows * 32;         // one warp per row; exact multiple of 512
    int block = 512;
    int grid  = total_threads / block;      // 6250, no remainder
    tp_uniform_fused_kernel<<<grid, block>>>(x0, x1, coeff, idx, out);
}

// round 12
// speedup vs baseline: 1.0406x; 1.0177x over previous
#include <cuda_runtime.h>

// TensorProductUniform3x1d:
//   B=100000, NSEG=4, U=128, NPATH=20
//   out[b, i2, :] += c[p] * x0[b, i0[p], :] * x1[b, i1[p], :]
//
// FINAL: exact R9 configuration — the best-measured kernel (dur_us 90.6).
//   * float4 accesses (128-bit; narrower widths regressed)
//   * one warp per row, 8 front-batched loads (2 rows/warp regressed)
//   * default cache policy (.cs / L2::256B regressed or neutral)
//   * linear CTA ordering (persistent grid-stride regressed)
//   * 512-thread blocks, 2 CTAs/SM (block scan 256/512/1024 -> 512 best)
//   * fused per-block W build in shared memory (single launch)

#define NSEG 4
#define U 128
#define NPATH 20

__global__ __launch_bounds__(512, 2)
void tp_uniform_fused_kernel(const float4* __restrict__ x0,
                             const float4* __restrict__ x1,
                             const float*  __restrict__ coeff,
                             const int*    __restrict__ idx,
                             float4* __restrict__ out,
                             int nrows) {
    __shared__ float sW[NSEG * NSEG * NSEG];

    // Build W[i2][i0][i1] = sum_p coeff[p] * [idx[p]==(i0,i1,i2)]
    int t = threadIdx.x;
    if (t < NSEG * NSEG * NSEG) {
        int i2 = t >> 4;
        int i0 = (t >> 2) & 3;
        int i1 = t & 3;
        float w = 0.0f;
        #pragma unroll
        for (int p = 0; p < NPATH; p++) {
            int p0 = __ldg(&idx[3 * p + 0]);
            int p1 = __ldg(&idx[3 * p + 1]);
            int p2 = __ldg(&idx[3 * p + 2]);
            if (p0 == i0 && p1 == i1 && p2 == i2) w += __ldg(&coeff[p]);
        }
        sW[t] = w;
    }
    __syncthreads();

    int gid  = blockIdx.x * blockDim.x + threadIdx.x;
    int row  = gid >> 5;
    int lane = gid & 31;
    if (row >= nrows) return;

    size_t base = (size_t)row * (NSEG * U / 4) + lane;  // float4 units

    // Front-batch all 8 loads (default cache policy — measured best).
    float4 a[NSEG], b[NSEG];
    #pragma unroll
    for (int s = 0; s < NSEG; s++) a[s] = __ldg(&x0[base + s * (U / 4)]);
    #pragma unroll
    for (int s = 0; s < NSEG; s++) b[s] = __ldg(&x1[base + s * (U / 4)]);

    // out[i2] = sum_{i0} a[i0] * ( sum_{i1} W[i2][i0][i1] * b[i1] )
    #pragma unroll
    for (int i2 = 0; i2 < NSEG; i2++) {
        float4 acc = make_float4(0.f, 0.f, 0.f, 0.f);
        #pragma unroll
        for (int i0 = 0; i0 < NSEG; i0++) {
            float4 tt = make_float4(0.f, 0.f, 0.f, 0.f);
            #pragma unroll
            for (int i1 = 0; i1 < NSEG; i1++) {
                float w = sW[(i2 * NSEG + i0) * NSEG + i1];
                tt.x = fmaf(w, b[i1].x, tt.x);
                tt.y = fmaf(w, b[i1].y, tt.y);
                tt.z = fmaf(w, b[i1].z, tt.z);
                tt.w = fmaf(w, b[i1].w, tt.w);
            }
            acc.x = fmaf(a[i0].x, tt.x, acc.x);
            acc.y = fmaf(a[i0].y, tt.y, acc.y);
            acc.z = fmaf(a[i0].z, tt.z, acc.z);
            acc.w = fmaf(a[i0].w, tt.w, acc.w);
        }
        out[base + i2 * (U / 4)] = acc;
    }
}

extern "C" void kernel_launch(void* const* d_in, const int* in_sizes, int n_in,
                              void* d_out, int out_size) {
    const float4* x0    = (const float4*)d_in[0];
    const float4* x1    = (const float4*)d_in[1];
    const float*  coeff = (const float*)d_in[2];
    const int*    idx   = (const int*)d_in[3];
    float4*       out   = (float4*)d_out;

    int nrows = in_sizes[0] / (NSEG * U);   // 100000

    int total_threads = nrows * 32;         // one warp per row
    int block = 512;
    int grid  = (total_threads + block - 1) / block;
    tp_uniform_fused_kernel<<<grid, block>>>(x0, x1, coeff, idx, out, nrows);
}